// round 2
// baseline (speedup 1.0000x reference)
#include <cuda_runtime.h>
#include <math.h>

#define DMODEL 1024
#define NH     16
#define DEPTH  64
#define BATCH  2
#define SEQ    2048
#define MROWS  (BATCH*SEQ)   // 4096

// Scratch (allocation-free rule: __device__ globals)
__device__ float g_Qh[BATCH*NH*SEQ*DEPTH];
__device__ float g_Kh[BATCH*NH*SEQ*DEPTH];
__device__ float g_Vh[BATCH*NH*SEQ*DEPTH];
__device__ float g_Oc[MROWS*DMODEL];

// ---------------------------------------------------------------------------
// C = A[M,1024] @ W[1024,1024]^T + bias, M=4096.
// 128x128 block tile, BK=8, 8x8 per-thread microtile, 256 threads.
// SPLIT: write output in [B,H,S,depth] layout for the attention stage.
// ---------------------------------------------------------------------------
template<bool SPLIT>
__global__ __launch_bounds__(256)
void gemm_bias_k(const float* __restrict__ A, const float* __restrict__ W,
                 const float* __restrict__ bias, float* __restrict__ C)
{
    __shared__ float As[8][128];   // [k][m]
    __shared__ float Ws[8][128];   // [k][n]
    const int tid = threadIdx.x;
    const int tx  = tid & 15;      // 0..15 -> 8 cols each
    const int ty  = tid >> 4;      // 0..15 -> 8 rows each
    const int bm  = blockIdx.y * 128;
    const int bn  = blockIdx.x * 128;

    const int lr = tid >> 1;          // 0..127
    const int lc = (tid & 1) << 2;    // 0 or 4
    const float* Ap = A + (size_t)(bm + lr) * DMODEL + lc;
    const float* Wp = W + (size_t)(bn + lr) * DMODEL + lc;

    float acc[8][8] = {};

    for (int k0 = 0; k0 < DMODEL; k0 += 8) {
        float4 av = *(const float4*)(Ap + k0);
        float4 wv = *(const float4*)(Wp + k0);
        As[lc+0][lr] = av.x; As[lc+1][lr] = av.y;
        As[lc+2][lr] = av.z; As[lc+3][lr] = av.w;
        Ws[lc+0][lr] = wv.x; Ws[lc+1][lr] = wv.y;
        Ws[lc+2][lr] = wv.z; Ws[lc+3][lr] = wv.w;
        __syncthreads();
#pragma unroll
        for (int k = 0; k < 8; ++k) {
            float4 a0 = *(const float4*)&As[k][ty*8];
            float4 a1 = *(const float4*)&As[k][ty*8+4];
            float4 b0 = *(const float4*)&Ws[k][tx*8];
            float4 b1 = *(const float4*)&Ws[k][tx*8+4];
            float ar[8] = {a0.x,a0.y,a0.z,a0.w,a1.x,a1.y,a1.z,a1.w};
            float br[8] = {b0.x,b0.y,b0.z,b0.w,b1.x,b1.y,b1.z,b1.w};
#pragma unroll
            for (int i = 0; i < 8; ++i)
#pragma unroll
                for (int j = 0; j < 8; ++j)
                    acc[i][j] = fmaf(ar[i], br[j], acc[i][j]);
        }
        __syncthreads();
    }

    if (SPLIT) {
#pragma unroll
        for (int i = 0; i < 8; ++i) {
            int row = bm + ty*8 + i;
            int b   = row >> 11;          // /SEQ
            int s   = row & (SEQ-1);
#pragma unroll
            for (int j = 0; j < 8; ++j) {
                int col = bn + tx*8 + j;
                int h = col >> 6;
                int d = col & 63;
                C[(((size_t)(b*NH + h))*SEQ + s)*DEPTH + d] = acc[i][j] + bias[col];
            }
        }
    } else {
#pragma unroll
        for (int i = 0; i < 8; ++i) {
            int row = bm + ty*8 + i;
            float* cp = C + (size_t)row * DMODEL + bn + tx*8;
            float4 bi0 = *(const float4*)(bias + bn + tx*8);
            float4 bi1 = *(const float4*)(bias + bn + tx*8 + 4);
            float4 w0 = make_float4(acc[i][0]+bi0.x, acc[i][1]+bi0.y,
                                    acc[i][2]+bi0.z, acc[i][3]+bi0.w);
            float4 w1 = make_float4(acc[i][4]+bi1.x, acc[i][5]+bi1.y,
                                    acc[i][6]+bi1.z, acc[i][7]+bi1.w);
            *(float4*)(cp)     = w0;
            *(float4*)(cp + 4) = w1;
        }
    }
}

// ---------------------------------------------------------------------------
// Flash-style attention: one block per (b*H+h, q-tile of 64 rows).
// 256 threads, 4x4 microtile per thread. Online softmax.
// Smem: Qst[d][r] 16K + Kst[d][c] 16K (reused as P[r][c]) + Vs[c][dd] 16K = 48K
// Output written in concat-head layout [B*S, DMODEL] for the final GEMM.
// ---------------------------------------------------------------------------
__global__ __launch_bounds__(256)
void attn_k(const float* __restrict__ Qh, const float* __restrict__ Kh,
            const float* __restrict__ Vh, const float* __restrict__ mask,
            float* __restrict__ Oc)
{
    __shared__ float Qst[64][64];  // [d][r]
    __shared__ float Kst[64][64];  // [d][c], reused as P[r][c]
    __shared__ float Vs [64][64];  // [c][dd]

    const int tid = threadIdx.x;
    const int tx  = tid & 15;     // 4 cols each
    const int ty  = tid >> 4;     // 4 rows each
    const int bh  = blockIdx.x;   // 0..31
    const int qt  = blockIdx.y;   // 0..31
    const int b   = bh >> 4;
    const int h   = bh & 15;

    // Load Q tile transposed: Qst[d][r] = Q[r][d]
    const float* Qbase = Qh + ((size_t)bh * SEQ + qt*64) * DEPTH;
    for (int i = tid; i < 64*16; i += 256) {
        int r  = i >> 4;
        int d4 = (i & 15) << 2;
        float4 qv = *(const float4*)(Qbase + r*DEPTH + d4);
        Qst[d4+0][r] = qv.x; Qst[d4+1][r] = qv.y;
        Qst[d4+2][r] = qv.z; Qst[d4+3][r] = qv.w;
    }

    float o[4][4] = {};
    float mrow[4], lrow[4];
#pragma unroll
    for (int i = 0; i < 4; ++i) { mrow[i] = -INFINITY; lrow[i] = 0.f; }

    const float* mbase = mask + ((size_t)b * SEQ + qt*64 + ty*4) * SEQ;
    __syncthreads();

    for (int kt = 0; kt < SEQ/64; ++kt) {
        const float* Kb = Kh + ((size_t)bh * SEQ + kt*64) * DEPTH;
        const float* Vb = Vh + ((size_t)bh * SEQ + kt*64) * DEPTH;
        for (int i = tid; i < 64*16; i += 256) {
            int c  = i >> 4;
            int d4 = (i & 15) << 2;
            float4 kv = *(const float4*)(Kb + c*DEPTH + d4);
            Kst[d4+0][c] = kv.x; Kst[d4+1][c] = kv.y;
            Kst[d4+2][c] = kv.z; Kst[d4+3][c] = kv.w;
            *(float4*)&Vs[c][d4] = *(const float4*)(Vb + c*DEPTH + d4);
        }
        __syncthreads();

        // scores: s[i][j] = sum_d Q[r][d]*K[c][d]
        float s[4][4] = {};
#pragma unroll 16
        for (int d = 0; d < 64; ++d) {
            float4 qv = *(const float4*)&Qst[d][ty*4];
            float4 kv = *(const float4*)&Kst[d][tx*4];
            float qa[4] = {qv.x,qv.y,qv.z,qv.w};
            float ka[4] = {kv.x,kv.y,kv.z,kv.w};
#pragma unroll
            for (int i = 0; i < 4; ++i)
#pragma unroll
                for (int j = 0; j < 4; ++j)
                    s[i][j] = fmaf(qa[i], ka[j], s[i][j]);
        }

        // scale + additive mask
#pragma unroll
        for (int i = 0; i < 4; ++i) {
            float4 mv = *(const float4*)(mbase + (size_t)i*SEQ + kt*64 + tx*4);
            s[i][0] = fmaf(mv.x, -1e9f, s[i][0]*0.125f);
            s[i][1] = fmaf(mv.y, -1e9f, s[i][1]*0.125f);
            s[i][2] = fmaf(mv.z, -1e9f, s[i][2]*0.125f);
            s[i][3] = fmaf(mv.w, -1e9f, s[i][3]*0.125f);
        }
        __syncthreads();  // all Kst reads done before P overwrite

        // online softmax (row groups = 16 consecutive lanes sharing ty)
#pragma unroll
        for (int i = 0; i < 4; ++i) {
            float tm = fmaxf(fmaxf(s[i][0], s[i][1]), fmaxf(s[i][2], s[i][3]));
#pragma unroll
            for (int off = 8; off > 0; off >>= 1)
                tm = fmaxf(tm, __shfl_xor_sync(0xffffffffu, tm, off));
            float mn    = fmaxf(mrow[i], tm);
            float alpha = __expf(mrow[i] - mn);
            mrow[i] = mn;
            float ls = 0.f;
#pragma unroll
            for (int j = 0; j < 4; ++j) { s[i][j] = __expf(s[i][j] - mn); ls += s[i][j]; }
#pragma unroll
            for (int off = 8; off > 0; off >>= 1)
                ls += __shfl_xor_sync(0xffffffffu, ls, off);
            lrow[i] = lrow[i]*alpha + ls;
#pragma unroll
            for (int j = 0; j < 4; ++j) o[i][j] *= alpha;
        }

        // write P into Kst as [r][c]
#pragma unroll
        for (int i = 0; i < 4; ++i)
            *(float4*)&Kst[ty*4+i][tx*4] = make_float4(s[i][0],s[i][1],s[i][2],s[i][3]);
        __syncthreads();

        // o += P @ V
#pragma unroll 8
        for (int c4 = 0; c4 < 16; ++c4) {
            float4 p[4], vv[4];
#pragma unroll
            for (int i = 0; i < 4; ++i) p[i]  = *(const float4*)&Kst[ty*4+i][c4*4];
#pragma unroll
            for (int ci = 0; ci < 4; ++ci) vv[ci] = *(const float4*)&Vs[c4*4+ci][tx*4];
            float pa[4][4] = {{p[0].x,p[0].y,p[0].z,p[0].w},
                              {p[1].x,p[1].y,p[1].z,p[1].w},
                              {p[2].x,p[2].y,p[2].z,p[2].w},
                              {p[3].x,p[3].y,p[3].z,p[3].w}};
            float va[4][4] = {{vv[0].x,vv[0].y,vv[0].z,vv[0].w},
                              {vv[1].x,vv[1].y,vv[1].z,vv[1].w},
                              {vv[2].x,vv[2].y,vv[2].z,vv[2].w},
                              {vv[3].x,vv[3].y,vv[3].z,vv[3].w}};
#pragma unroll
            for (int ci = 0; ci < 4; ++ci)
#pragma unroll
                for (int i = 0; i < 4; ++i)
#pragma unroll
                    for (int j = 0; j < 4; ++j)
                        o[i][j] = fmaf(pa[i][ci], va[ci][j], o[i][j]);
        }
        __syncthreads();  // protect Kst/Vs for next tile load
    }

    // epilogue: concat heads -> Oc[b*S + s][h*64 + dd]
    const int orow = qt*64 + ty*4;
#pragma unroll
    for (int i = 0; i < 4; ++i) {
        float inv = 1.f / lrow[i];
        float4 w = make_float4(o[i][0]*inv, o[i][1]*inv, o[i][2]*inv, o[i][3]*inv);
        *(float4*)(Oc + ((size_t)b*SEQ + orow + i)*DMODEL + h*DEPTH + tx*4) = w;
    }
}

// ---------------------------------------------------------------------------
extern "C" void kernel_launch(void* const* d_in, const int* in_sizes, int n_in,
                              void* d_out, int out_size)
{
    const float* v    = (const float*)d_in[0];
    const float* k    = (const float*)d_in[1];
    const float* q    = (const float*)d_in[2];
    const float* mask = (const float*)d_in[3];
    const float* wq   = (const float*)d_in[4];
    const float* bq   = (const float*)d_in[5];
    const float* wk   = (const float*)d_in[6];
    const float* bk   = (const float*)d_in[7];
    const float* wv   = (const float*)d_in[8];
    const float* bv   = (const float*)d_in[9];
    const float* wo   = (const float*)d_in[10];
    const float* bo   = (const float*)d_in[11];
    float* out = (float*)d_out;

    float *Qh, *Kh, *Vh, *Oc;
    cudaGetSymbolAddress((void**)&Qh, g_Qh);
    cudaGetSymbolAddress((void**)&Kh, g_Kh);
    cudaGetSymbolAddress((void**)&Vh, g_Vh);
    cudaGetSymbolAddress((void**)&Oc, g_Oc);

    dim3 gg(DMODEL/128, MROWS/128);  // (8, 32)
    gemm_bias_k<true ><<<gg, 256>>>(q, wq, bq, Qh);
    gemm_bias_k<true ><<<gg, 256>>>(k, wk, bk, Kh);
    gemm_bias_k<true ><<<gg, 256>>>(v, wv, bv, Vh);

    dim3 ga(BATCH*NH, SEQ/64);       // (32, 32)
    attn_k<<<ga, 256>>>(Qh, Kh, Vh, mask, Oc);

    gemm_bias_k<false><<<gg, 256>>>(Oc, wo, bo, out);
}

// round 3
// speedup vs baseline: 2.0070x; 2.0070x over previous
#include <cuda_runtime.h>
#include <math.h>
#include <stdint.h>

#define DMODEL 1024
#define NH     16
#define DEPTH  64
#define BATCH  2
#define SEQ    2048
#define MROWS  (BATCH*SEQ)   // 4096

// Scratch (allocation-free rule: __device__ globals)
__device__ float g_Qh[BATCH*NH*SEQ*DEPTH];
__device__ float g_Kh[BATCH*NH*SEQ*DEPTH];
__device__ float g_Vh[BATCH*NH*SEQ*DEPTH];
__device__ float g_Oc[MROWS*DMODEL];

__device__ __forceinline__ float to_tf32(float x) {
    float r;
    asm("cvt.rna.tf32.f32 %0, %1;" : "=f"(r) : "f"(x));
    return r;
}

__device__ __forceinline__ void mma8(float c[4], const uint32_t a[4], const uint32_t b[2]) {
    asm volatile(
        "mma.sync.aligned.m16n8k8.row.col.f32.tf32.tf32.f32 "
        "{%0,%1,%2,%3},{%4,%5,%6,%7},{%8,%9},{%0,%1,%2,%3};\n"
        : "+f"(c[0]), "+f"(c[1]), "+f"(c[2]), "+f"(c[3])
        : "r"(a[0]), "r"(a[1]), "r"(a[2]), "r"(a[3]), "r"(b[0]), "r"(b[1]));
}

// ---------------------------------------------------------------------------
// C = A[4096,1024] @ W[1024,1024]^T + bias, tf32 tensor-core GEMM.
// 128x128 block tile, BK=16, 8 warps, each warp 64x32 (4 mtiles x 4 ntiles).
// Smem stride 20 floats: frag access addr = 20g + t -> perfect bank perm.
// ---------------------------------------------------------------------------
template<bool SPLIT>
__global__ __launch_bounds__(256)
void gemm_tc(const float* __restrict__ A, const float* __restrict__ W,
             const float* __restrict__ bias, float* __restrict__ C)
{
    __shared__ float As[128][20];
    __shared__ float Ws[128][20];
    const int tid  = threadIdx.x;
    const int lane = tid & 31, wid = tid >> 5;
    const int wm   = wid >> 2, wn = wid & 3;
    const int g    = lane >> 2, t = lane & 3;
    const int bm   = blockIdx.y * 128, bn = blockIdx.x * 128;

    const int lr = tid >> 1;          // 0..127
    const int lc = (tid & 1) * 8;     // 0 or 8
    const float* Ap = A + (size_t)(bm + lr) * DMODEL + lc;
    const float* Wp = W + (size_t)(bn + lr) * DMODEL + lc;

    float4 pa0 = *(const float4*)(Ap),     pa1 = *(const float4*)(Ap + 4);
    float4 pw0 = *(const float4*)(Wp),     pw1 = *(const float4*)(Wp + 4);

    float acc[4][4][4] = {};

    for (int k0 = 0;;) {
        // commit prefetched tile (tf32-rounded) to smem
        *(float4*)&As[lr][lc]   = make_float4(to_tf32(pa0.x), to_tf32(pa0.y), to_tf32(pa0.z), to_tf32(pa0.w));
        *(float4*)&As[lr][lc+4] = make_float4(to_tf32(pa1.x), to_tf32(pa1.y), to_tf32(pa1.z), to_tf32(pa1.w));
        *(float4*)&Ws[lr][lc]   = make_float4(to_tf32(pw0.x), to_tf32(pw0.y), to_tf32(pw0.z), to_tf32(pw0.w));
        *(float4*)&Ws[lr][lc+4] = make_float4(to_tf32(pw1.x), to_tf32(pw1.y), to_tf32(pw1.z), to_tf32(pw1.w));
        __syncthreads();

        const int kn = k0 + 16;
        if (kn < DMODEL) {
            pa0 = *(const float4*)(Ap + kn); pa1 = *(const float4*)(Ap + kn + 4);
            pw0 = *(const float4*)(Wp + kn); pw1 = *(const float4*)(Wp + kn + 4);
        }

#pragma unroll
        for (int ks = 0; ks < 2; ++ks) {
            const int kb = ks * 8;
            uint32_t af[4][4], bf[4][2];
#pragma unroll
            for (int mt = 0; mt < 4; ++mt) {
                const int r = wm*64 + mt*16 + g;
                af[mt][0] = __float_as_uint(As[r  ][kb + t]);
                af[mt][1] = __float_as_uint(As[r+8][kb + t]);
                af[mt][2] = __float_as_uint(As[r  ][kb + t + 4]);
                af[mt][3] = __float_as_uint(As[r+8][kb + t + 4]);
            }
#pragma unroll
            for (int nt = 0; nt < 4; ++nt) {
                const int n = wn*32 + nt*8 + g;
                bf[nt][0] = __float_as_uint(Ws[n][kb + t]);
                bf[nt][1] = __float_as_uint(Ws[n][kb + t + 4]);
            }
#pragma unroll
            for (int mt = 0; mt < 4; ++mt)
#pragma unroll
                for (int nt = 0; nt < 4; ++nt)
                    mma8(acc[mt][nt], af[mt], bf[nt]);
        }

        k0 = kn;
        if (k0 >= DMODEL) break;
        __syncthreads();
    }

    // epilogue
#pragma unroll
    for (int mt = 0; mt < 4; ++mt) {
        const int r0 = bm + wm*64 + mt*16 + g;   // r0 and r0+8 share same batch b
#pragma unroll
        for (int nt = 0; nt < 4; ++nt) {
            const int c0 = bn + wn*32 + nt*8 + t*2;
            const float b0 = bias[c0], b1 = bias[c0 + 1];
            const float v00 = acc[mt][nt][0] + b0, v01 = acc[mt][nt][1] + b1;
            const float v10 = acc[mt][nt][2] + b0, v11 = acc[mt][nt][3] + b1;
            if (SPLIT) {
                const int bb = r0 >> 11;
                const int s  = r0 & (SEQ - 1);
                const int h  = c0 >> 6;
                const int d  = c0 & 63;
                float* p0 = C + (((size_t)(bb*NH + h))*SEQ + s    )*DEPTH + d;
                float* p1 = C + (((size_t)(bb*NH + h))*SEQ + s + 8)*DEPTH + d;
                *(float2*)p0 = make_float2(v00, v01);
                *(float2*)p1 = make_float2(v10, v11);
            } else {
                *(float2*)(C + (size_t)r0      * DMODEL + c0) = make_float2(v00, v01);
                *(float2*)(C + (size_t)(r0+8)  * DMODEL + c0) = make_float2(v10, v11);
            }
        }
    }
}

// ---------------------------------------------------------------------------
// Flash attention, tf32 tensor cores.
// Block = 128 threads (4 warps), q-tile 64 (16 rows/warp), kv-chunk 32.
// Smem: Qs[64][68] + Ks[32][68] + Vt[64][36] + Ps[64][36] = 44544 B.
// ---------------------------------------------------------------------------
__global__ __launch_bounds__(128)
void attn_tc(const float* __restrict__ Qh, const float* __restrict__ Kh,
             const float* __restrict__ Vh, const float* __restrict__ mask,
             float* __restrict__ Oc)
{
    __shared__ float Qs[64][68];
    __shared__ float Ks[32][68];
    __shared__ float Vt[64][36];
    __shared__ float Ps[64][36];

    const int tid  = threadIdx.x;
    const int lane = tid & 31, w = tid >> 5;
    const int g    = lane >> 2, t = lane & 3;
    const int bh   = blockIdx.x;         // b*NH + h
    const int qt   = blockIdx.y;
    const int b    = bh >> 4, h = bh & 15;

    // load Q tile (tf32-rounded)
    const float* Qb = Qh + ((size_t)bh * SEQ + qt*64) * DEPTH;
    for (int i = tid; i < 1024; i += 128) {
        const int r = i >> 4, c4 = (i & 15) * 4;
        float4 v = *(const float4*)(Qb + r*DEPTH + c4);
        *(float4*)&Qs[r][c4] = make_float4(to_tf32(v.x), to_tf32(v.y), to_tf32(v.z), to_tf32(v.w));
    }

    float oacc[8][4] = {};
    float m0 = -INFINITY, m1 = -INFINITY, l0 = 0.f, l1 = 0.f;

    const float* Kb0 = Kh + (size_t)bh * SEQ * DEPTH;
    const float* Vb0 = Vh + (size_t)bh * SEQ * DEPTH;
    const float* Mb  = mask + ((size_t)b * SEQ + qt*64) * SEQ;
    const int pr = w*16 + g;

    __syncthreads();

    for (int kt = 0; kt < SEQ/32; ++kt) {
        // load K chunk [32][64]
        for (int i = tid; i < 512; i += 128) {
            const int r = i >> 4, c4 = (i & 15) * 4;
            float4 v = *(const float4*)(Kb0 + (size_t)(kt*32 + r)*DEPTH + c4);
            *(float4*)&Ks[r][c4] = make_float4(to_tf32(v.x), to_tf32(v.y), to_tf32(v.z), to_tf32(v.w));
        }
        // load V chunk transposed: Vt[d][c]  (conflict-free: c = lane)
        for (int i = tid; i < 512; i += 128) {
            const int c = i & 31, d4 = (i >> 5) * 4;
            float4 v = *(const float4*)(Vb0 + (size_t)(kt*32 + c)*DEPTH + d4);
            Vt[d4+0][c] = to_tf32(v.x); Vt[d4+1][c] = to_tf32(v.y);
            Vt[d4+2][c] = to_tf32(v.z); Vt[d4+3][c] = to_tf32(v.w);
        }
        __syncthreads();

        // S = Q @ K^T  (16x32 per warp)
        float sacc[4][4] = {};
#pragma unroll
        for (int ks = 0; ks < 8; ++ks) {
            const int kb = ks * 8;
            uint32_t af[4];
            af[0] = __float_as_uint(Qs[w*16 + g    ][kb + t]);
            af[1] = __float_as_uint(Qs[w*16 + g + 8][kb + t]);
            af[2] = __float_as_uint(Qs[w*16 + g    ][kb + t + 4]);
            af[3] = __float_as_uint(Qs[w*16 + g + 8][kb + t + 4]);
#pragma unroll
            for (int nt = 0; nt < 4; ++nt) {
                uint32_t bf[2];
                bf[0] = __float_as_uint(Ks[nt*8 + g][kb + t]);
                bf[1] = __float_as_uint(Ks[nt*8 + g][kb + t + 4]);
                mma8(sacc[nt], af, bf);
            }
        }

        // scale + additive mask
#pragma unroll
        for (int nt = 0; nt < 4; ++nt) {
            const int c0 = kt*32 + nt*8 + t*2;
            float2 mlo = *(const float2*)(Mb + (size_t)(w*16 + g    )*SEQ + c0);
            float2 mhi = *(const float2*)(Mb + (size_t)(w*16 + g + 8)*SEQ + c0);
            sacc[nt][0] = fmaf(mlo.x, -1e9f, sacc[nt][0]*0.125f);
            sacc[nt][1] = fmaf(mlo.y, -1e9f, sacc[nt][1]*0.125f);
            sacc[nt][2] = fmaf(mhi.x, -1e9f, sacc[nt][2]*0.125f);
            sacc[nt][3] = fmaf(mhi.y, -1e9f, sacc[nt][3]*0.125f);
        }

        // online softmax (2 rows per thread, quad reduction over lane%4)
        float rm0 = -INFINITY, rm1 = -INFINITY;
#pragma unroll
        for (int nt = 0; nt < 4; ++nt) {
            rm0 = fmaxf(rm0, fmaxf(sacc[nt][0], sacc[nt][1]));
            rm1 = fmaxf(rm1, fmaxf(sacc[nt][2], sacc[nt][3]));
        }
        rm0 = fmaxf(rm0, __shfl_xor_sync(0xffffffffu, rm0, 1));
        rm0 = fmaxf(rm0, __shfl_xor_sync(0xffffffffu, rm0, 2));
        rm1 = fmaxf(rm1, __shfl_xor_sync(0xffffffffu, rm1, 1));
        rm1 = fmaxf(rm1, __shfl_xor_sync(0xffffffffu, rm1, 2));

        const float mn0 = fmaxf(m0, rm0), mn1 = fmaxf(m1, rm1);
        const float a0  = __expf(m0 - mn0), a1 = __expf(m1 - mn1);
        m0 = mn0; m1 = mn1;

        float sum0 = 0.f, sum1 = 0.f;
#pragma unroll
        for (int nt = 0; nt < 4; ++nt) {
            sacc[nt][0] = __expf(sacc[nt][0] - mn0); sum0 += sacc[nt][0];
            sacc[nt][1] = __expf(sacc[nt][1] - mn0); sum0 += sacc[nt][1];
            sacc[nt][2] = __expf(sacc[nt][2] - mn1); sum1 += sacc[nt][2];
            sacc[nt][3] = __expf(sacc[nt][3] - mn1); sum1 += sacc[nt][3];
        }
        sum0 += __shfl_xor_sync(0xffffffffu, sum0, 1);
        sum0 += __shfl_xor_sync(0xffffffffu, sum0, 2);
        sum1 += __shfl_xor_sync(0xffffffffu, sum1, 1);
        sum1 += __shfl_xor_sync(0xffffffffu, sum1, 2);
        l0 = l0*a0 + sum0;
        l1 = l1*a1 + sum1;
#pragma unroll
        for (int nt = 0; nt < 8; ++nt) {
            oacc[nt][0] *= a0; oacc[nt][1] *= a0;
            oacc[nt][2] *= a1; oacc[nt][3] *= a1;
        }

        // P -> smem (warp-private rows, tf32-rounded)
#pragma unroll
        for (int nt = 0; nt < 4; ++nt) {
            *(float2*)&Ps[pr    ][nt*8 + t*2] = make_float2(to_tf32(sacc[nt][0]), to_tf32(sacc[nt][1]));
            *(float2*)&Ps[pr + 8][nt*8 + t*2] = make_float2(to_tf32(sacc[nt][2]), to_tf32(sacc[nt][3]));
        }
        __syncwarp();

        // O += P @ V   (16x64 per warp, K=32)
#pragma unroll
        for (int ks = 0; ks < 4; ++ks) {
            const int kb = ks * 8;
            uint32_t af[4];
            af[0] = __float_as_uint(Ps[pr    ][kb + t]);
            af[1] = __float_as_uint(Ps[pr + 8][kb + t]);
            af[2] = __float_as_uint(Ps[pr    ][kb + t + 4]);
            af[3] = __float_as_uint(Ps[pr + 8][kb + t + 4]);
#pragma unroll
            for (int nt = 0; nt < 8; ++nt) {
                uint32_t bf[2];
                bf[0] = __float_as_uint(Vt[nt*8 + g][kb + t]);
                bf[1] = __float_as_uint(Vt[nt*8 + g][kb + t + 4]);
                mma8(oacc[nt], af, bf);
            }
        }
        __syncthreads();
    }

    // epilogue: normalize + concat heads -> Oc[b*S + s][h*64 + d]
    const float inv0 = 1.f / l0, inv1 = 1.f / l1;
    const size_t row0 = (size_t)b*SEQ + qt*64 + w*16 + g;
#pragma unroll
    for (int nt = 0; nt < 8; ++nt) {
        const int c = h*64 + nt*8 + t*2;
        *(float2*)(Oc + row0     * DMODEL + c) = make_float2(oacc[nt][0]*inv0, oacc[nt][1]*inv0);
        *(float2*)(Oc + (row0+8) * DMODEL + c) = make_float2(oacc[nt][2]*inv1, oacc[nt][3]*inv1);
    }
}

// ---------------------------------------------------------------------------
extern "C" void kernel_launch(void* const* d_in, const int* in_sizes, int n_in,
                              void* d_out, int out_size)
{
    const float* v    = (const float*)d_in[0];
    const float* k    = (const float*)d_in[1];
    const float* q    = (const float*)d_in[2];
    const float* mask = (const float*)d_in[3];
    const float* wq   = (const float*)d_in[4];
    const float* bq   = (const float*)d_in[5];
    const float* wk   = (const float*)d_in[6];
    const float* bk   = (const float*)d_in[7];
    const float* wv   = (const float*)d_in[8];
    const float* bv   = (const float*)d_in[9];
    const float* wo   = (const float*)d_in[10];
    const float* bo   = (const float*)d_in[11];
    float* out = (float*)d_out;

    float *Qh, *Kh, *Vh, *Oc;
    cudaGetSymbolAddress((void**)&Qh, g_Qh);
    cudaGetSymbolAddress((void**)&Kh, g_Kh);
    cudaGetSymbolAddress((void**)&Vh, g_Vh);
    cudaGetSymbolAddress((void**)&Oc, g_Oc);

    dim3 gg(DMODEL/128, MROWS/128);  // (8, 32)
    gemm_tc<true ><<<gg, 256>>>(q, wq, bq, Qh);
    gemm_tc<true ><<<gg, 256>>>(k, wk, bk, Kh);
    gemm_tc<true ><<<gg, 256>>>(v, wv, bv, Vh);

    dim3 ga(BATCH*NH, SEQ/64);       // (32, 32)
    attn_tc<<<ga, 128>>>(Qh, Kh, Vh, mask, Oc);

    gemm_tc<false><<<gg, 256>>>(Oc, wo, bo, out);
}